// round 15
// baseline (speedup 1.0000x reference)
#include <cuda_runtime.h>
#include <cuda_fp16.h>
#include <cstdint>
#include <math.h>

#define BB 4
#define CC 64
#define HH 128
#define WW 128
#define HWp (HH*WW)
#define OCA 27

// scratch (no allocations allowed)
__device__ __half g_xt16[BB*HWp*CC];   // x in NHWC, fp16 (128B per pixel)
__device__ __half g_x16[BB*CC*HWp];    // x in NCHW, fp16 (for pool)
__device__ float  g_off[BB*OCA*HWp];   // offset conv out (mask channels = 2*sigmoid)
__device__ __half g_wact16[BB*CC*HWp]; // exp(sigmoid(align conv)) NCHW, fp16

// ============================ helpers =======================================
__device__ __forceinline__ uint32_t s2u(const void* p) {
    uint32_t a;
    asm("{ .reg .u64 t; cvta.to.shared.u64 t, %1; cvt.u32.u64 %0, t; }" : "=r"(a) : "l"(p));
    return a;
}
#define LDSM_X4(a, addr) \
    asm volatile("ldmatrix.sync.aligned.m8n8.x4.shared.b16 {%0,%1,%2,%3}, [%4];" \
        : "=r"((a)[0]), "=r"((a)[1]), "=r"((a)[2]), "=r"((a)[3]) : "r"(addr))
#define MMA_F16(d, a, b) \
    asm volatile("mma.sync.aligned.m16n8k16.row.col.f32.f16.f16.f32 " \
        "{%0,%1,%2,%3}, {%4,%5,%6,%7}, {%8,%9}, {%0,%1,%2,%3};" \
        : "+f"((d)[0]), "+f"((d)[1]), "+f"((d)[2]), "+f"((d)[3]) \
        : "r"((a)[0]), "r"((a)[1]), "r"((a)[2]), "r"((a)[3]), \
          "r"((b)[0]), "r"((b)[1]))
#define BAR_SYNC(id, cnt)   asm volatile("bar.sync %0, %1;"   :: "r"(id), "r"(cnt) : "memory")
#define BAR_ARRIVE(id, cnt) asm volatile("bar.arrive %0, %1;" :: "r"(id), "r"(cnt) : "memory")

__device__ __forceinline__ float fast_sigmoid(float v) {
    return __fdividef(1.f, 1.f + __expf(-v));
}

// fp16 A-tile: [128 rows][8 chunks of 16B]; chunk ^= (row&7)
__device__ __forceinline__ uint32_t a16_off(int row, int chunk) {
    return (uint32_t)(row*128 + (((chunk ^ (row & 7)) & 7) << 4));
}

__constant__ int cDY[9] = {-1,-1,-1, 0,0,0, 1,1,1};
__constant__ int cDX[9] = {-1, 0, 1,-1,0,1,-1,0,1};

// ---------------------------------------------------------------------------
// Kernel 0: NCHW fp32 -> NHWC fp16 (+ NCHW fp16 copy for pool)
// ---------------------------------------------------------------------------
__global__ void k_transpose(const float* __restrict__ x) {
    __shared__ float tile[32][33];
    int b  = blockIdx.z;
    int c0 = blockIdx.y * 32;
    int p0 = blockIdx.x * 32;
    int tx = threadIdx.x, ty = threadIdx.y;
    #pragma unroll
    for (int i = ty; i < 32; i += 8) {
        float v = x[(b*CC + c0 + i)*HWp + p0 + tx];
        tile[i][tx] = v;
        g_x16[(b*CC + c0 + i)*HWp + p0 + tx] = __float2half_rn(v);
    }
    __syncthreads();
    #pragma unroll
    for (int i = ty; i < 32; i += 8)
        g_xt16[(b*HWp + p0 + i)*CC + c0 + tx] = __float2half_rn(tile[tx][i]);
}

// ===========================================================================
// Kernel A: 3x3 offset conv 64->27 (pad 32) via fp16 m16n8k16 (fp32-D),
// pipelined. 16 warps: wm = wid>>1 (16px), wn = wid&1 (16 oc). 2 CTAs/SM.
// ===========================================================================
#define A_WFRAG  0
#define A_ABUF   36864                 // 36*4*32*8
#define A_SMEM   (A_ABUF + 2*16384)   // 69632

__global__ __launch_bounds__(512, 2)
void k_offconv_mma(const float* __restrict__ w_off, const float* __restrict__ b_off) {
    extern __shared__ char smem[];
    uint32_t sb = s2u(smem);
    int tid = threadIdx.x;
    int wid = tid >> 5, lane = tid & 31;

    // WFRAG: [36 gks][4 ntg][32 lane] x 4 halves (k0,k0+1,k0+8,k0+9 ; n)
    for (int i = tid; i < 36*4*32; i += 512) {
        int l = i & 31, ntg = (i >> 5) & 3, gks = i >> 7;
        int k0 = gks*16 + (l & 3)*2;
        int n  = ntg*8 + (l >> 2);
        __half h[4];
        #pragma unroll
        for (int j = 0; j < 4; ++j) {
            int k = k0 + (j & 1) + (j >> 1)*8;
            int tap = k >> 6, c = k & 63;
            h[j] = (n < OCA) ? __float2half_rn(w_off[(n*CC + c)*9 + tap])
                             : __half(0.f);
        }
        *(uint2*)(smem + (size_t)i*8) = *(uint2*)h;
    }
    __syncthreads();

    int wm = wid >> 1, wn = wid & 1;
    int lrow_in = (lane & 7) + (lane & 8);
    int g2 = lane >> 4;
    int ch8 = tid & 7;            // 8-channel group
    int pxh = tid >> 3;           // 0..63, +64 for pass 1
    const int ntiles = BB*HH;

    for (int tile = blockIdx.x; tile < ntiles; tile += gridDim.x) {
        int h = tile & (HH-1);
        int b = tile >> 7;
        const char* xbb = (const char*)(g_xt16 + (size_t)b*HWp*CC);

        float acc[2][4];
        #pragma unroll
        for (int nt = 0; nt < 2; ++nt)
            #pragma unroll
            for (int i = 0; i < 4; ++i) acc[nt][i] = 0.f;

        __syncthreads();
        {   // prologue: tap 0 -> buf0
            int row = h + cDY[0], dxk = cDX[0];
            #pragma unroll
            for (int j = 0; j < 2; ++j) {
                int px = pxh + j*64;
                int col = px + dxk;
                uint4 v = make_uint4(0,0,0,0);
                if ((unsigned)row < HH && (unsigned)col < WW)
                    v = *(const uint4*)(xbb + (((size_t)row*WW + col) << 7) + (ch8 << 4));
                *(uint4*)(smem + A_ABUF + a16_off(px, ch8)) = v;
            }
        }
        __syncthreads();

        for (int tap = 0; tap < 9; ++tap) {
            int cur = tap & 1, nxt = cur ^ 1;
            bool haven = (tap + 1 < 9);

            uint4 pv[2];
            if (haven) {
                int row = h + cDY[tap+1], dxk = cDX[tap+1];
                #pragma unroll
                for (int j = 0; j < 2; ++j) {
                    int col = pxh + j*64 + dxk;
                    uint4 v = make_uint4(0,0,0,0);
                    if ((unsigned)row < HH && (unsigned)col < WW)
                        v = *(const uint4*)(xbb + (((size_t)row*WW + col) << 7) + (ch8 << 4));
                    pv[j] = v;
                }
            }

            uint32_t bufc = sb + A_ABUF + (uint32_t)cur*16384;
            #pragma unroll
            for (int ks = 0; ks < 4; ++ks) {
                int gks = tap*4 + ks;
                uint32_t a[4];
                LDSM_X4(a, bufc + a16_off(wm*16 + lrow_in, ks*2 + g2));
                #pragma unroll
                for (int nt = 0; nt < 2; ++nt) {
                    uint32_t bfr[2];
                    *(uint2*)bfr = *(const uint2*)(smem + A_WFRAG
                        + (((size_t)(gks*4 + wn*2 + nt)*32 + lane) << 3));
                    MMA_F16(acc[nt], a, bfr);
                }
            }

            if (haven) {
                char* bufn = smem + A_ABUF + nxt*16384;
                #pragma unroll
                for (int j = 0; j < 2; ++j)
                    *(uint4*)(bufn + a16_off(pxh + j*64, ch8)) = pv[j];
            }
            __syncthreads();
        }

        #pragma unroll
        for (int nt = 0; nt < 2; ++nt) {
            int ocb = wn*16 + nt*8 + (lane & 3)*2;
            int px  = wm*16 + (lane >> 2);
            #pragma unroll
            for (int dd = 0; dd < 4; ++dd) {
                int oc = ocb + (dd & 1);
                int pxx = px + (dd >> 1)*8;
                if (oc < OCA) {
                    float val = acc[nt][dd] + __ldg(b_off + oc);
                    if (oc >= 18) val = 2.f * fast_sigmoid(val);
                    g_off[((b*OCA + oc)*HH + h)*WW + pxx] = val;
                }
            }
        }
    }
}

// ===========================================================================
// Kernel B: deformable sampling + fp16 MMA, WARP-SPECIALIZED 4/12.
// Warps 0-3: MMA consumers (each 32 px = 2 mtiles, all 64 oc, 64 MMA/tap).
// Warps 4-15: gather producers (12 warps; meta + bilinear -> 4-slot ring).
// Named barriers: 1 = producer-internal (384); full slot s: 2+s (512);
// empty slot s: 6+s (512). No block-wide barriers in the tile loop.
// smem: WFRAG 73728 + 4x ABUF 16384 + 2x meta 2048 = 143360. 1 CTA/SM.
// ===========================================================================
#define D_WFRAG  0
#define D_ABUF   73728
#define D_META   (D_ABUF + 4*16384)   // 139264; slot = 1024 (half wts) + 1024 (int2)
#define D_SMEM   (D_META + 2*2048)    // 143360

// bilinear combine of 4 fp16 corner vectors (8 ch), pure fp16 HFMA2
__device__ __forceinline__ uint4 bilerp8h(uint4 c00, uint4 c01, uint4 c10, uint4 c11,
                                          uint2 wp) {
    const __half* hw = (const __half*)&wp;
    __half2 w00 = __half2half2(hw[0]);
    __half2 w01 = __half2half2(hw[1]);
    __half2 w10 = __half2half2(hw[2]);
    __half2 w11 = __half2half2(hw[3]);
    uint4 out;
    const uint32_t* p00 = (const uint32_t*)&c00;
    const uint32_t* p01 = (const uint32_t*)&c01;
    const uint32_t* p10 = (const uint32_t*)&c10;
    const uint32_t* p11 = (const uint32_t*)&c11;
    uint32_t* po = (uint32_t*)&out;
    #pragma unroll
    for (int hp = 0; hp < 4; ++hp) {
        __half2 v = __hmul2(*(const __half2*)&p11[hp], w11);
        v = __hfma2(*(const __half2*)&p10[hp], w10, v);
        v = __hfma2(*(const __half2*)&p01[hp], w01, v);
        v = __hfma2(*(const __half2*)&p00[hp], w00, v);
        po[hp] = *(const uint32_t*)&v;
    }
    return out;
}

__global__ __launch_bounds__(512, 1)
void k_deform_mma(const float* __restrict__ w_align, const float* __restrict__ b_align) {
    extern __shared__ char smem[];
    uint32_t sb = s2u(smem);
    int tid = threadIdx.x;
    int wid = tid >> 5, lane = tid & 31;

    // WFRAG: [36 gks][8 nt][32 lane] x 4 halves
    for (int i = tid; i < 36*8*32; i += 512) {
        int l = i & 31, ntg = (i >> 5) & 7, gks = i >> 8;
        int k0 = gks*16 + (l & 3)*2;
        int n  = ntg*8 + (l >> 2);
        __half h[4];
        #pragma unroll
        for (int j = 0; j < 4; ++j) {
            int k = k0 + (j & 1) + (j >> 1)*8;
            int tap = k >> 6, c = k & 63;
            h[j] = __float2half_rn(w_align[(n*CC + c)*9 + tap]);
        }
        *(uint2*)(smem + (size_t)i*8) = *(uint2*)h;
    }
    __syncthreads();

    const int ntiles = BB*HH;

    if (wid < 4) {
        // ================= CONSUMER (MMA) warps =================
        int wm = wid;               // 32-px block
        int lrow_in = (lane & 7) + (lane & 8);
        int g2 = lane >> 4;
        int g = 0;
        for (int tile = blockIdx.x; tile < ntiles; tile += gridDim.x) {
            int h = tile & (HH-1);
            int b = tile >> 7;
            float acc[2][8][4];
            #pragma unroll
            for (int mt = 0; mt < 2; ++mt)
                #pragma unroll
                for (int nt = 0; nt < 8; ++nt)
                    #pragma unroll
                    for (int i = 0; i < 4; ++i) acc[mt][nt][i] = 0.f;

            for (int tap = 0; tap < 9; ++tap, ++g) {
                int s = g & 3;
                BAR_SYNC(2 + s, 512);   // wait full
                uint32_t bufc = sb + D_ABUF + (uint32_t)s*16384;
                #pragma unroll
                for (int ks = 0; ks < 4; ++ks) {
                    int gks = tap*4 + ks;
                    uint32_t a0[4], a1[4];
                    LDSM_X4(a0, bufc + a16_off(wm*32      + lrow_in, ks*2 + g2));
                    LDSM_X4(a1, bufc + a16_off(wm*32 + 16 + lrow_in, ks*2 + g2));
                    #pragma unroll
                    for (int nt = 0; nt < 8; ++nt) {
                        uint32_t bfr[2];
                        *(uint2*)bfr = *(const uint2*)(smem + D_WFRAG
                            + (((size_t)(gks*8 + nt)*32 + lane) << 3));
                        MMA_F16(acc[0][nt], a0, bfr);
                        MMA_F16(acc[1][nt], a1, bfr);
                    }
                }
                BAR_ARRIVE(6 + s, 512); // mark empty
            }

            // epilogue (fp16 wact)
            #pragma unroll
            for (int mt = 0; mt < 2; ++mt) {
                int px = wm*32 + mt*16 + (lane >> 2);
                #pragma unroll
                for (int nt = 0; nt < 8; ++nt) {
                    int ocb = nt*8 + (lane & 3)*2;
                    #pragma unroll
                    for (int dd = 0; dd < 4; ++dd) {
                        int oc = ocb + (dd & 1);
                        int pxx = px + (dd >> 1)*8;
                        float wv = acc[mt][nt][dd] + __ldg(b_align + oc);
                        g_wact16[((b*CC + oc)*HH + h)*WW + pxx] =
                            __float2half_rn(__expf(fast_sigmoid(wv)));
                    }
                }
            }
        }
    } else {
        // ================= PRODUCER (gather) warps =================
        int ptid = tid - 128;          // 0..383
        int g = 0;
        for (int tile = blockIdx.x; tile < ntiles; tile += gridDim.x) {
            int h = tile & (HH-1);
            int b = tile >> 7;
            const char* xbb = (const char*)(g_xt16 + (size_t)b*HWp*CC);

            for (int tap = 0; tap < 9; ++tap, ++g) {
                int s  = g & 3;
                int ms = tap & 1;
                char* meta = smem + D_META + ms*2048;
                // meta for this tap (first 128 producer threads)
                if (ptid < 128) {
                    int px = ptid;
                    const float* ob = g_off + (size_t)b*OCA*HWp + (size_t)h*WW + px;
                    float dy = ob[(2*tap    )*HWp];
                    float dx = ob[(2*tap + 1)*HWp];
                    float m  = ob[(18 + tap )*HWp];
                    float Y = (float)(h  + cDY[tap]) + dy;
                    float X = (float)(px + cDX[tap]) + dx;
                    float yf = floorf(Y), xf = floorf(X);
                    int y0 = (int)yf, x0 = (int)xf;
                    float fy = Y - yf, fx = X - xf;
                    bool y0v = ((unsigned)y0     < HH);
                    bool y1v = ((unsigned)(y0+1) < HH);
                    bool x0v = ((unsigned)x0     < WW);
                    bool x1v = ((unsigned)(x0+1) < WW);
                    __half hw[4];
                    hw[0] = __float2half_rn((1.f-fy)*(1.f-fx) * m * (y0v && x0v));
                    hw[1] = __float2half_rn((1.f-fy)*fx       * m * (y0v && x1v));
                    hw[2] = __float2half_rn(fy*(1.f-fx)       * m * (y1v && x0v));
                    hw[3] = __float2half_rn(fy*fx             * m * (y1v && x1v));
                    int yc0 = min(max(y0, 0), HH-1), yc1 = min(max(y0+1, 0), HH-1);
                    int xc0 = min(max(x0, 0), WW-1), xc1 = min(max(x0+1, 0), WW-1);
                    int base = (yc0*WW + xc0) << 7;      // fp16: 128B/px
                    int sx   = (xc1 - xc0) << 7;         // 0 or 128
                    int sy   = (yc1 - yc0) * (WW << 7);  // 0 or 16384
                    ((uint2*)meta)[px] = *(uint2*)hw;
                    ((int2*)(meta + 1024))[px] = make_int2(base, (sy << 2) | sx);
                }
                BAR_SYNC(1, 384);       // meta ready (producer-internal)

                if (g >= 4) BAR_SYNC(6 + s, 512);   // wait empty

                char* buf = smem + D_ABUF + s*16384;
                // 1024 (px,ch8) items over 384 threads
                for (int i = ptid; i < 1024; i += 384) {
                    int px = i >> 3, ch8 = i & 7;
                    int qo = ch8 << 4;
                    uint2 wp = ((const uint2*)meta)[px];
                    int2  pp = ((const int2*)(meta + 1024))[px];
                    int sx = pp.y & 0xffff;
                    int sy = (pp.y & 0x10000) ? 16384 : 0;
                    uint4 c00 = *(const uint4*)(xbb + pp.x + qo);
                    uint4 c01 = *(const uint4*)(xbb + pp.x + sx + qo);
                    uint4 c10 = *(const uint4*)(xbb + pp.x + sy + qo);
                    uint4 c11 = *(const uint4*)(xbb + pp.x + sx + sy + qo);
                    *(uint4*)(buf + a16_off(px, ch8)) = bilerp8h(c00,c01,c10,c11,wp);
                }
                BAR_ARRIVE(2 + s, 512);  // mark full
            }
        }
    }
}

// ---------------------------------------------------------------------------
// Kernel C: pooled ratio; 4 outputs/thread along oh with row-sum reuse.
// x and wact both read as fp16.
// ---------------------------------------------------------------------------
__global__ void k_pool(float* __restrict__ out) {
    int t = blockIdx.x * 256 + threadIdx.x;
    if (t >= BB*CC*16*64) return;
    int ow  = t & 63;
    int ohg = (t >> 6) & 15;
    int c   = (t >> 10) & 63;
    int b   = t >> 16;
    const __half* wp = g_wact16 + ((size_t)b*CC + c)*HWp;
    const __half* xp = g_x16    + ((size_t)b*CC + c)*HWp;
    int oh0 = ohg * 4;
    int c0 = 2*ow - 1;
    float rsW[9], rsX[9];
    #pragma unroll
    for (int j = 0; j < 9; ++j) {
        int r = 2*oh0 - 1 + j;
        float sw = 0.f, sx = 0.f;
        if ((unsigned)r < HH) {
            #pragma unroll
            for (int dc = 0; dc < 3; ++dc) {
                int cl = c0 + dc;
                if ((unsigned)cl < WW) {
                    float wv = __half2float(wp[r*WW + cl]);
                    sw += wv;
                    sx = fmaf(wv, __half2float(xp[r*WW + cl]), sx);
                }
            }
        }
        rsW[j] = sw; rsX[j] = sx;
    }
    #pragma unroll
    for (int i = 0; i < 4; ++i) {
        float den = rsW[2*i] + rsW[2*i+1] + rsW[2*i+2];
        float num = rsX[2*i] + rsX[2*i+1] + rsX[2*i+2];
        out[((b*CC + c)*64 + oh0 + i)*64 + ow] = num / den;
    }
}

// ---------------------------------------------------------------------------
extern "C" void kernel_launch(void* const* d_in, const int* in_sizes, int n_in,
                              void* d_out, int out_size) {
    const float* x       = (const float*)d_in[0];
    const float* w_off   = (const float*)d_in[1];
    const float* b_off   = (const float*)d_in[2];
    const float* w_align = (const float*)d_in[3];
    const float* b_align = (const float*)d_in[4];
    float* out = (float*)d_out;
    (void)in_sizes; (void)n_in; (void)out_size;

    static_assert(A_SMEM <= 113664, "A smem (2 CTAs)");
    static_assert(D_SMEM <= 227328, "D smem");

    cudaFuncSetAttribute(k_offconv_mma, cudaFuncAttributeMaxDynamicSharedMemorySize, A_SMEM);
    cudaFuncSetAttribute(k_deform_mma,  cudaFuncAttributeMaxDynamicSharedMemorySize, D_SMEM);

    dim3 tg(HWp/32, CC/32, BB);
    k_transpose<<<tg, dim3(32, 8)>>>(x);

    k_offconv_mma<<<296, 512, A_SMEM>>>(w_off, b_off);

    k_deform_mma<<<148, 512, D_SMEM>>>(w_align, b_align);

    k_pool<<<(BB*CC*16*64 + 255)/256, 256>>>(out);
}

// round 16
// speedup vs baseline: 1.0652x; 1.0652x over previous
#include <cuda_runtime.h>
#include <cuda_fp16.h>
#include <cstdint>
#include <math.h>

#define BB 4
#define CC 64
#define HH 128
#define WW 128
#define HWp (HH*WW)
#define OCA 27

// scratch (no allocations allowed)
__device__ __half g_xt16[BB*HWp*CC];   // x in NHWC, fp16 (128B per pixel)
__device__ __half g_x16[BB*CC*HWp];    // x in NCHW, fp16 (for pool)
__device__ float  g_off[BB*OCA*HWp];   // offset conv out (mask channels = 2*sigmoid)
__device__ __half g_wact16[BB*CC*HWp]; // exp(sigmoid(align conv)) NCHW, fp16

// ============================ helpers =======================================
__device__ __forceinline__ uint32_t s2u(const void* p) {
    uint32_t a;
    asm("{ .reg .u64 t; cvta.to.shared.u64 t, %1; cvt.u32.u64 %0, t; }" : "=r"(a) : "l"(p));
    return a;
}
#define LDSM_X4(a, addr) \
    asm volatile("ldmatrix.sync.aligned.m8n8.x4.shared.b16 {%0,%1,%2,%3}, [%4];" \
        : "=r"((a)[0]), "=r"((a)[1]), "=r"((a)[2]), "=r"((a)[3]) : "r"(addr))
#define MMA_F16(d, a, b) \
    asm volatile("mma.sync.aligned.m16n8k16.row.col.f32.f16.f16.f32 " \
        "{%0,%1,%2,%3}, {%4,%5,%6,%7}, {%8,%9}, {%0,%1,%2,%3};" \
        : "+f"((d)[0]), "+f"((d)[1]), "+f"((d)[2]), "+f"((d)[3]) \
        : "r"((a)[0]), "r"((a)[1]), "r"((a)[2]), "r"((a)[3]), \
          "r"((b)[0]), "r"((b)[1]))
#define BAR_SYNC(id, cnt)   asm volatile("bar.sync %0, %1;"   :: "r"(id), "r"(cnt) : "memory")
#define BAR_ARRIVE(id, cnt) asm volatile("bar.arrive %0, %1;" :: "r"(id), "r"(cnt) : "memory")

__device__ __forceinline__ float fast_sigmoid(float v) {
    return __fdividef(1.f, 1.f + __expf(-v));
}

// fp16 A-tile: [128 rows][8 chunks of 16B]; chunk ^= (row&7)
__device__ __forceinline__ uint32_t a16_off(int row, int chunk) {
    return (uint32_t)(row*128 + (((chunk ^ (row & 7)) & 7) << 4));
}

__constant__ int cDY[9] = {-1,-1,-1, 0,0,0, 1,1,1};
__constant__ int cDX[9] = {-1, 0, 1,-1,0,1,-1,0,1};

// ---------------------------------------------------------------------------
// Kernel 0: NCHW fp32 -> NHWC fp16 (+ NCHW fp16 copy for pool)
// ---------------------------------------------------------------------------
__global__ void k_transpose(const float* __restrict__ x) {
    __shared__ float tile[32][33];
    int b  = blockIdx.z;
    int c0 = blockIdx.y * 32;
    int p0 = blockIdx.x * 32;
    int tx = threadIdx.x, ty = threadIdx.y;
    #pragma unroll
    for (int i = ty; i < 32; i += 8) {
        float v = x[(b*CC + c0 + i)*HWp + p0 + tx];
        tile[i][tx] = v;
        g_x16[(b*CC + c0 + i)*HWp + p0 + tx] = __float2half_rn(v);
    }
    __syncthreads();
    #pragma unroll
    for (int i = ty; i < 32; i += 8)
        g_xt16[(b*HWp + p0 + i)*CC + c0 + tx] = __float2half_rn(tile[tx][i]);
}

// ===========================================================================
// Kernel A: 3x3 offset conv 64->27 (pad 32) via fp16 m16n8k16 (fp32-D),
// pipelined. 16 warps: wm = wid>>1 (16px), wn = wid&1 (16 oc). 2 CTAs/SM.
// ===========================================================================
#define A_WFRAG  0
#define A_ABUF   36864                 // 36*4*32*8
#define A_SMEM   (A_ABUF + 2*16384)   // 69632

__global__ __launch_bounds__(512, 2)
void k_offconv_mma(const float* __restrict__ w_off, const float* __restrict__ b_off) {
    extern __shared__ char smem[];
    uint32_t sb = s2u(smem);
    int tid = threadIdx.x;
    int wid = tid >> 5, lane = tid & 31;

    // WFRAG: [36 gks][4 ntg][32 lane] x 4 halves (k0,k0+1,k0+8,k0+9 ; n)
    for (int i = tid; i < 36*4*32; i += 512) {
        int l = i & 31, ntg = (i >> 5) & 3, gks = i >> 7;
        int k0 = gks*16 + (l & 3)*2;
        int n  = ntg*8 + (l >> 2);
        __half h[4];
        #pragma unroll
        for (int j = 0; j < 4; ++j) {
            int k = k0 + (j & 1) + (j >> 1)*8;
            int tap = k >> 6, c = k & 63;
            h[j] = (n < OCA) ? __float2half_rn(w_off[(n*CC + c)*9 + tap])
                             : __half(0.f);
        }
        *(uint2*)(smem + (size_t)i*8) = *(uint2*)h;
    }
    __syncthreads();

    int wm = wid >> 1, wn = wid & 1;
    int lrow_in = (lane & 7) + (lane & 8);
    int g2 = lane >> 4;
    int ch8 = tid & 7;            // 8-channel group
    int pxh = tid >> 3;           // 0..63, +64 for pass 1
    const int ntiles = BB*HH;

    for (int tile = blockIdx.x; tile < ntiles; tile += gridDim.x) {
        int h = tile & (HH-1);
        int b = tile >> 7;
        const char* xbb = (const char*)(g_xt16 + (size_t)b*HWp*CC);

        float acc[2][4];
        #pragma unroll
        for (int nt = 0; nt < 2; ++nt)
            #pragma unroll
            for (int i = 0; i < 4; ++i) acc[nt][i] = 0.f;

        __syncthreads();
        {   // prologue: tap 0 -> buf0
            int row = h + cDY[0], dxk = cDX[0];
            #pragma unroll
            for (int j = 0; j < 2; ++j) {
                int px = pxh + j*64;
                int col = px + dxk;
                uint4 v = make_uint4(0,0,0,0);
                if ((unsigned)row < HH && (unsigned)col < WW)
                    v = *(const uint4*)(xbb + (((size_t)row*WW + col) << 7) + (ch8 << 4));
                *(uint4*)(smem + A_ABUF + a16_off(px, ch8)) = v;
            }
        }
        __syncthreads();

        for (int tap = 0; tap < 9; ++tap) {
            int cur = tap & 1, nxt = cur ^ 1;
            bool haven = (tap + 1 < 9);

            uint4 pv[2];
            if (haven) {
                int row = h + cDY[tap+1], dxk = cDX[tap+1];
                #pragma unroll
                for (int j = 0; j < 2; ++j) {
                    int col = pxh + j*64 + dxk;
                    uint4 v = make_uint4(0,0,0,0);
                    if ((unsigned)row < HH && (unsigned)col < WW)
                        v = *(const uint4*)(xbb + (((size_t)row*WW + col) << 7) + (ch8 << 4));
                    pv[j] = v;
                }
            }

            uint32_t bufc = sb + A_ABUF + (uint32_t)cur*16384;
            #pragma unroll
            for (int ks = 0; ks < 4; ++ks) {
                int gks = tap*4 + ks;
                uint32_t a[4];
                LDSM_X4(a, bufc + a16_off(wm*16 + lrow_in, ks*2 + g2));
                #pragma unroll
                for (int nt = 0; nt < 2; ++nt) {
                    uint32_t bfr[2];
                    *(uint2*)bfr = *(const uint2*)(smem + A_WFRAG
                        + (((size_t)(gks*4 + wn*2 + nt)*32 + lane) << 3));
                    MMA_F16(acc[nt], a, bfr);
                }
            }

            if (haven) {
                char* bufn = smem + A_ABUF + nxt*16384;
                #pragma unroll
                for (int j = 0; j < 2; ++j)
                    *(uint4*)(bufn + a16_off(pxh + j*64, ch8)) = pv[j];
            }
            __syncthreads();
        }

        #pragma unroll
        for (int nt = 0; nt < 2; ++nt) {
            int ocb = wn*16 + nt*8 + (lane & 3)*2;
            int px  = wm*16 + (lane >> 2);
            #pragma unroll
            for (int dd = 0; dd < 4; ++dd) {
                int oc = ocb + (dd & 1);
                int pxx = px + (dd >> 1)*8;
                if (oc < OCA) {
                    float val = acc[nt][dd] + __ldg(b_off + oc);
                    if (oc >= 18) val = 2.f * fast_sigmoid(val);
                    g_off[((b*OCA + oc)*HH + h)*WW + pxx] = val;
                }
            }
        }
    }
}

// ===========================================================================
// Kernel B: deformable sampling + fp16 MMA, WARP-SPECIALIZED 8/8 (R13).
// Warps 0-7: MMA consumers (wm = wid, 16px, all 64 oc = 8 nt).
// Warps 8-15: gather producers (meta + bilinear -> 4-slot ABUF ring).
// Named barriers: 1 = producer-internal (256); full slot s: 2+s (512);
// empty slot s: 6+s (512). No block-wide barriers in the tile loop.
// smem: WFRAG 73728 + 4x ABUF 16384 + 2x meta 2048 = 143360. 1 CTA/SM.
// ===========================================================================
#define D_WFRAG  0
#define D_ABUF   73728
#define D_META   (D_ABUF + 4*16384)   // 139264; slot = 1024 (half wts) + 1024 (int2)
#define D_SMEM   (D_META + 2*2048)    // 143360

// bilinear combine of 4 fp16 corner vectors (8 ch), pure fp16 HFMA2
__device__ __forceinline__ uint4 bilerp8h(uint4 c00, uint4 c01, uint4 c10, uint4 c11,
                                          uint2 wp) {
    const __half* hw = (const __half*)&wp;
    __half2 w00 = __half2half2(hw[0]);
    __half2 w01 = __half2half2(hw[1]);
    __half2 w10 = __half2half2(hw[2]);
    __half2 w11 = __half2half2(hw[3]);
    uint4 out;
    const uint32_t* p00 = (const uint32_t*)&c00;
    const uint32_t* p01 = (const uint32_t*)&c01;
    const uint32_t* p10 = (const uint32_t*)&c10;
    const uint32_t* p11 = (const uint32_t*)&c11;
    uint32_t* po = (uint32_t*)&out;
    #pragma unroll
    for (int hp = 0; hp < 4; ++hp) {
        __half2 v = __hmul2(*(const __half2*)&p11[hp], w11);
        v = __hfma2(*(const __half2*)&p10[hp], w10, v);
        v = __hfma2(*(const __half2*)&p01[hp], w01, v);
        v = __hfma2(*(const __half2*)&p00[hp], w00, v);
        po[hp] = *(const uint32_t*)&v;
    }
    return out;
}

__global__ __launch_bounds__(512, 1)
void k_deform_mma(const float* __restrict__ w_align, const float* __restrict__ b_align) {
    extern __shared__ char smem[];
    uint32_t sb = s2u(smem);
    int tid = threadIdx.x;
    int wid = tid >> 5, lane = tid & 31;

    // WFRAG: [36 gks][8 nt][32 lane] x 4 halves
    for (int i = tid; i < 36*8*32; i += 512) {
        int l = i & 31, ntg = (i >> 5) & 7, gks = i >> 8;
        int k0 = gks*16 + (l & 3)*2;
        int n  = ntg*8 + (l >> 2);
        __half h[4];
        #pragma unroll
        for (int j = 0; j < 4; ++j) {
            int k = k0 + (j & 1) + (j >> 1)*8;
            int tap = k >> 6, c = k & 63;
            h[j] = __float2half_rn(w_align[(n*CC + c)*9 + tap]);
        }
        *(uint2*)(smem + (size_t)i*8) = *(uint2*)h;
    }
    __syncthreads();

    const int ntiles = BB*HH;

    if (wid < 8) {
        // ================= CONSUMER (MMA) warps =================
        int wm = wid;
        int lrow_in = (lane & 7) + (lane & 8);
        int g2 = lane >> 4;
        int g = 0;
        for (int tile = blockIdx.x; tile < ntiles; tile += gridDim.x) {
            int h = tile & (HH-1);
            int b = tile >> 7;
            float acc[8][4];
            #pragma unroll
            for (int nt = 0; nt < 8; ++nt)
                #pragma unroll
                for (int i = 0; i < 4; ++i) acc[nt][i] = 0.f;

            for (int tap = 0; tap < 9; ++tap, ++g) {
                int s = g & 3;
                BAR_SYNC(2 + s, 512);   // wait full
                uint32_t bufc = sb + D_ABUF + (uint32_t)s*16384;
                #pragma unroll
                for (int ks = 0; ks < 4; ++ks) {
                    int gks = tap*4 + ks;
                    uint32_t a[4];
                    LDSM_X4(a, bufc + a16_off(wm*16 + lrow_in, ks*2 + g2));
                    #pragma unroll
                    for (int nt = 0; nt < 8; ++nt) {
                        uint32_t bfr[2];
                        *(uint2*)bfr = *(const uint2*)(smem + D_WFRAG
                            + (((size_t)(gks*8 + nt)*32 + lane) << 3));
                        MMA_F16(acc[nt], a, bfr);
                    }
                }
                BAR_ARRIVE(6 + s, 512); // mark empty
            }

            // epilogue (fp16 wact)
            int px = wm*16 + (lane >> 2);
            #pragma unroll
            for (int nt = 0; nt < 8; ++nt) {
                int ocb = nt*8 + (lane & 3)*2;
                #pragma unroll
                for (int dd = 0; dd < 4; ++dd) {
                    int oc = ocb + (dd & 1);
                    int pxx = px + (dd >> 1)*8;
                    float wv = acc[nt][dd] + __ldg(b_align + oc);
                    g_wact16[((b*CC + oc)*HH + h)*WW + pxx] =
                        __float2half_rn(__expf(fast_sigmoid(wv)));
                }
            }
        }
    } else {
        // ================= PRODUCER (gather) warps =================
        int ptid = tid - 256;          // 0..255
        int ch8 = ptid & 7;
        int pxq = ptid >> 3;           // 0..31; px = pxq + j*32
        int g = 0;
        for (int tile = blockIdx.x; tile < ntiles; tile += gridDim.x) {
            int h = tile & (HH-1);
            int b = tile >> 7;
            const char* xbb = (const char*)(g_xt16 + (size_t)b*HWp*CC);

            for (int tap = 0; tap < 9; ++tap, ++g) {
                int s  = g & 3;
                int ms = tap & 1;
                char* meta = smem + D_META + ms*2048;
                // meta for this tap (128 producer threads)
                if (ptid < 128) {
                    int px = ptid;
                    const float* ob = g_off + (size_t)b*OCA*HWp + (size_t)h*WW + px;
                    float dy = ob[(2*tap    )*HWp];
                    float dx = ob[(2*tap + 1)*HWp];
                    float m  = ob[(18 + tap )*HWp];
                    float Y = (float)(h  + cDY[tap]) + dy;
                    float X = (float)(px + cDX[tap]) + dx;
                    float yf = floorf(Y), xf = floorf(X);
                    int y0 = (int)yf, x0 = (int)xf;
                    float fy = Y - yf, fx = X - xf;
                    bool y0v = ((unsigned)y0     < HH);
                    bool y1v = ((unsigned)(y0+1) < HH);
                    bool x0v = ((unsigned)x0     < WW);
                    bool x1v = ((unsigned)(x0+1) < WW);
                    __half hw[4];
                    hw[0] = __float2half_rn((1.f-fy)*(1.f-fx) * m * (y0v && x0v));
                    hw[1] = __float2half_rn((1.f-fy)*fx       * m * (y0v && x1v));
                    hw[2] = __float2half_rn(fy*(1.f-fx)       * m * (y1v && x0v));
                    hw[3] = __float2half_rn(fy*fx             * m * (y1v && x1v));
                    int yc0 = min(max(y0, 0), HH-1), yc1 = min(max(y0+1, 0), HH-1);
                    int xc0 = min(max(x0, 0), WW-1), xc1 = min(max(x0+1, 0), WW-1);
                    int base = (yc0*WW + xc0) << 7;      // fp16: 128B/px
                    int sx   = (xc1 - xc0) << 7;         // 0 or 128
                    int sy   = (yc1 - yc0) * (WW << 7);  // 0 or 16384
                    ((uint2*)meta)[px] = *(uint2*)hw;
                    ((int2*)(meta + 1024))[px] = make_int2(base, (sy << 2) | sx);
                }
                BAR_SYNC(1, 256);       // meta ready (producer-internal)

                if (g >= 4) BAR_SYNC(6 + (s & 3), 512);   // wait empty

                char* buf = smem + D_ABUF + s*16384;
                int qo = ch8 << 4;
                // 4 items, corner loads batched in pairs for MLP
                #pragma unroll
                for (int jp = 0; jp < 2; ++jp) {
                    int pxA = pxq + (jp*2    )*32;
                    int pxB = pxq + (jp*2 + 1)*32;
                    uint2 wpA = ((const uint2*)meta)[pxA];
                    uint2 wpB = ((const uint2*)meta)[pxB];
                    int2  ppA = ((const int2*)(meta + 1024))[pxA];
                    int2  ppB = ((const int2*)(meta + 1024))[pxB];
                    int sxA = ppA.y & 0xffff, syA = (ppA.y & 0x10000) ? 16384 : 0;
                    int sxB = ppB.y & 0xffff, syB = (ppB.y & 0x10000) ? 16384 : 0;
                    uint4 A0 = *(const uint4*)(xbb + ppA.x + qo);
                    uint4 A1 = *(const uint4*)(xbb + ppA.x + sxA + qo);
                    uint4 A2 = *(const uint4*)(xbb + ppA.x + syA + qo);
                    uint4 A3 = *(const uint4*)(xbb + ppA.x + sxA + syA + qo);
                    uint4 B0 = *(const uint4*)(xbb + ppB.x + qo);
                    uint4 B1 = *(const uint4*)(xbb + ppB.x + sxB + qo);
                    uint4 B2 = *(const uint4*)(xbb + ppB.x + syB + qo);
                    uint4 B3 = *(const uint4*)(xbb + ppB.x + sxB + syB + qo);
                    *(uint4*)(buf + a16_off(pxA, ch8)) = bilerp8h(A0,A1,A2,A3,wpA);
                    *(uint4*)(buf + a16_off(pxB, ch8)) = bilerp8h(B0,B1,B2,B3,wpB);
                }
                BAR_ARRIVE(2 + s, 512);  // mark full
            }
        }
    }
}

// ===========================================================================
// Kernel C: block-cooperative pool. Block = (b, c, 4 output rows):
// stages wact/x rows 2*oh0-1 .. 2*oh0+7 (9 rows x 128 cols, fp16) in smem
// via coalesced uint4 loads, then computes 4x64 outputs from smem.
// ===========================================================================
__global__ __launch_bounds__(256)
void k_pool(float* __restrict__ out) {
    __shared__ __half sw[9][128];
    __shared__ __half sx[9][128];
    int bid = blockIdx.x;          // 4096 blocks
    int ohg = bid & 15;
    int c   = (bid >> 4) & 63;
    int b   = bid >> 10;
    int tid = threadIdx.x;
    int oh0 = ohg * 4;

    const __half* wp = g_wact16 + ((size_t)b*CC + c)*HWp;
    const __half* xp = g_x16    + ((size_t)b*CC + c)*HWp;

    // load 9 rows x 128 halves (16 uint4 per row) for both arrays
    for (int i = tid; i < 9*16; i += 256) {
        int j = i >> 4, ch = i & 15;
        int r = 2*oh0 - 1 + j;
        uint4 vw = make_uint4(0,0,0,0);
        uint4 vx = make_uint4(0,0,0,0);
        if ((unsigned)r < HH) {
            vw = *(const uint4*)(wp + r*WW + ch*8);
            vx = *(const uint4*)(xp + r*WW + ch*8);
        }
        *(uint4*)(&sw[j][ch*8]) = vw;
        *(uint4*)(&sx[j][ch*8]) = vx;
    }
    __syncthreads();

    int ow = tid & 63;
    int i  = tid >> 6;             // 0..3
    int c0 = 2*ow - 1;
    float num = 0.f, den = 0.f;
    #pragma unroll
    for (int jj = 0; jj < 3; ++jj) {
        int row = 2*i + jj;        // smem row (global r = 2*(oh0+i)-1+jj)
        #pragma unroll
        for (int dc = 0; dc < 3; ++dc) {
            int cl = c0 + dc;
            if ((unsigned)cl < WW) {
                float wv = __half2float(sw[row][cl]);
                num = fmaf(wv, __half2float(sx[row][cl]), num);
                den += wv;
            }
        }
    }
    out[((b*CC + c)*64 + oh0 + i)*64 + ow] = num / den;
}

// ---------------------------------------------------------------------------
extern "C" void kernel_launch(void* const* d_in, const int* in_sizes, int n_in,
                              void* d_out, int out_size) {
    const float* x       = (const float*)d_in[0];
    const float* w_off   = (const float*)d_in[1];
    const float* b_off   = (const float*)d_in[2];
    const float* w_align = (const float*)d_in[3];
    const float* b_align = (const float*)d_in[4];
    float* out = (float*)d_out;
    (void)in_sizes; (void)n_in; (void)out_size;

    static_assert(A_SMEM <= 113664, "A smem (2 CTAs)");
    static_assert(D_SMEM <= 227328, "D smem");

    cudaFuncSetAttribute(k_offconv_mma, cudaFuncAttributeMaxDynamicSharedMemorySize, A_SMEM);
    cudaFuncSetAttribute(k_deform_mma,  cudaFuncAttributeMaxDynamicSharedMemorySize, D_SMEM);

    dim3 tg(HWp/32, CC/32, BB);
    k_transpose<<<tg, dim3(32, 8)>>>(x);

    k_offconv_mma<<<296, 512, A_SMEM>>>(w_off, b_off);

    k_deform_mma<<<148, 512, D_SMEM>>>(w_align, b_align);

    k_pool<<<BB*CC*16, 256>>>(out);
}